// round 8
// baseline (speedup 1.0000x reference)
#include <cuda_runtime.h>

// CRF loss, linear-domain scan — PERSISTENT version.
// Grid = 148 (one CTA per SM), 128 threads. Each CTA processes rows
// bid and bid+148 sequentially (solo CTA per SM -> no co-residency convoy).
// Thread j owns column j of E=exp(trans) (64 f32x2 regs), loaded ONCE.
// One __syncthreads per step. Deferred power-of-2 renorm every 4 steps.
// Final mean fused via atomic ticket (last CTA reduces).

namespace {
constexpr int TT = 128;
constexpr int SS = 1024;
constexpr int NB = 256;
constexpr int NCTA = 148;
constexpr int START_TAG = 126;
constexpr int END_TAG = 127;
}

typedef unsigned long long ull;
__device__ double g_part[NB];
__device__ unsigned int g_ticket;

__device__ __forceinline__ ull pack2f(float lo, float hi) {
    ull r;
    asm("mov.b64 %0, {%1, %2};" : "=l"(r) : "f"(lo), "f"(hi));
    return r;
}

// dot of shared alpha[0..127] with this thread's E column; 4 accumulators.
__device__ __forceinline__ float dotrow(const float* __restrict__ ar,
                                        const ull* __restrict__ E) {
    ull acc[4] = {0ull, 0ull, 0ull, 0ull};
    const double2* ap = reinterpret_cast<const double2*>(ar);
#pragma unroll
    for (int k = 0; k < 16; k++) {
        double2 a = ap[2 * k];
        double2 b = ap[2 * k + 1];
        ull a0 = __double_as_longlong(a.x);
        ull a1 = __double_as_longlong(a.y);
        ull b0 = __double_as_longlong(b.x);
        ull b1 = __double_as_longlong(b.y);
        asm("fma.rn.f32x2 %0, %1, %2, %0;" : "+l"(acc[0]) : "l"(a0), "l"(E[4 * k + 0]));
        asm("fma.rn.f32x2 %0, %1, %2, %0;" : "+l"(acc[1]) : "l"(a1), "l"(E[4 * k + 1]));
        asm("fma.rn.f32x2 %0, %1, %2, %0;" : "+l"(acc[2]) : "l"(b0), "l"(E[4 * k + 2]));
        asm("fma.rn.f32x2 %0, %1, %2, %0;" : "+l"(acc[3]) : "l"(b1), "l"(E[4 * k + 3]));
    }
    asm("add.rn.f32x2 %0, %0, %1;" : "+l"(acc[0]) : "l"(acc[2]));
    asm("add.rn.f32x2 %0, %0, %1;" : "+l"(acc[1]) : "l"(acc[3]));
    asm("add.rn.f32x2 %0, %0, %1;" : "+l"(acc[0]) : "l"(acc[1]));
    float lo, hi;
    asm("mov.b64 {%0, %1}, %2;" : "=f"(lo), "=f"(hi) : "l"(acc[0]));
    return lo + hi;
}

template <bool REN>
__device__ __forceinline__ void crf_step(const float* __restrict__ ar,
                                         float* __restrict__ aw,
                                         const ull* __restrict__ E,
                                         float expem, int j, float* red) {
    float v = dotrow(ar, E) * expem;
    aw[j] = v;
    if (REN) {
        int m;  // v >= 0: fp max == s32 max on bit patterns
        asm volatile("redux.sync.max.s32 %0, %1, 0xffffffff;"
                     : "=r"(m) : "r"(__float_as_int(v)));
        if ((j & 31) == 0) red[j >> 5] = __int_as_float(m);
    }
    __syncthreads();
}

__device__ __forceinline__ void consume_max(const float* red, int& le, float& sc) {
    float4 r4 = *reinterpret_cast<const float4*>(red);
    float mm = fmaxf(fmaxf(r4.x, r4.y), fmaxf(r4.z, r4.w));
    int ex = (__float_as_int(mm) >> 23) - 127;
    le += ex;
    sc = __int_as_float((127 - ex) << 23);
}

__global__ void __launch_bounds__(128, 1)
crf_scan_kernel(const float* __restrict__ em, const int* __restrict__ tags,
                const float* __restrict__ trans, float* __restrict__ out) {
    const int j = threadIdx.x;
    __shared__ __align__(16) float alpha[2][TT];
    __shared__ __align__(16) float red[8];
    __shared__ int s_last;

    // E column j in registers, packed (i, i+1) pairs — loaded ONCE, reused
    // for both rows this CTA processes.
    ull E[64];
#pragma unroll
    for (int k = 0; k < 64; k++) {
        float e0 = __expf(trans[(2 * k) * TT + j]);
        float e1 = __expf(trans[(2 * k + 1) * TT + j]);
        E[k] = pack2f(e0, e1);
    }

    // one-time: max of END transition row
    float tE = trans[END_TAG * TT + j];
    {
        float m = tE;
#pragma unroll
        for (int o = 16; o > 0; o >>= 1)
            m = fmaxf(m, __shfl_xor_sync(0xffffffffu, m, o));
        if ((j & 31) == 0) red[j >> 5] = m;
    }
    __syncthreads();
    const float mTE = fmaxf(fmaxf(red[0], red[1]), fmaxf(red[2], red[3]));
    const float eT = __expf(tE - mTE);

#pragma unroll 1
    for (int rr = 0; rr < 2; rr++) {
        const int b = blockIdx.x + rr * NCTA;
        if (b >= NB) break;

        const float* emb = em + (size_t)b * SS * TT;
        const int* tg = tags + b * SS;

        // ---- gold path score ----
        float gold = 0.f;
#pragma unroll
        for (int r = 0; r < SS / TT; r++) {
            int s = r * TT + j;
            int cur = tg[s];
            int prev = (s == 0) ? START_TAG : tg[s - 1];
            gold += emb[s * TT + cur] + trans[prev * TT + cur];
        }
        if (j == 0) gold += trans[tg[SS - 1] * TT + END_TAG];

        __syncthreads();  // red free of previous row's state
        if (j < 4) red[j] = 1.0f;  // first group: ex=0, sc=1
        alpha[0][j] = (j == START_TAG) ? 1.f : 0.f;
        __syncthreads();

        // ---- scan, t = 1..1023 ----
        int le = 0;
        float b0 = emb[1 * TT + j];
        float b1 = emb[2 * TT + j];
        float b2 = emb[3 * TT + j];
        float b3 = emb[4 * TT + j];
        float* a0p = alpha[0];
        float* a1p = alpha[1];

#pragma unroll 1
        for (int g = 0; g < 254; g++) {
            float sc;
            consume_max(red, le, sc);
            float e0 = __expf(b0) * sc;
            float e1 = __expf(b1);
            float e2 = __expf(b2);
            float e3 = __expf(b3);
            const int tn = 4 * g + 5;
            float n0 = emb[(tn + 0) * TT + j];
            float n1 = emb[(tn + 1) * TT + j];
            float n2 = emb[(tn + 2) * TT + j];
            float n3 = emb[(tn + 3) * TT + j];
            crf_step<false>(a0p, a1p, E, e0, j, red);
            crf_step<false>(a1p, a0p, E, e1, j, red);
            crf_step<false>(a0p, a1p, E, e2, j, red);
            crf_step<true >(a1p, a0p, E, e3, j, red);
            b0 = n0; b1 = n1; b2 = n2; b3 = n3;
        }
        // group 255: t = 1017..1020, prefetch tail
        {
            float sc;
            consume_max(red, le, sc);
            float e0 = __expf(b0) * sc;
            float e1 = __expf(b1);
            float e2 = __expf(b2);
            float e3 = __expf(b3);
            float n0 = emb[1021 * TT + j];
            float n1 = emb[1022 * TT + j];
            float n2 = emb[1023 * TT + j];
            crf_step<false>(a0p, a1p, E, e0, j, red);
            crf_step<false>(a1p, a0p, E, e1, j, red);
            crf_step<false>(a0p, a1p, E, e2, j, red);
            crf_step<true >(a1p, a0p, E, e3, j, red);
            b0 = n0; b1 = n1; b2 = n2;
        }
        // tail: t = 1021..1023 (final alpha in buffer 1)
        {
            float sc;
            consume_max(red, le, sc);
            float e0 = __expf(b0) * sc;
            float e1 = __expf(b1);
            float e2 = __expf(b2);
            crf_step<false>(a0p, a1p, E, e0, j, red);
            crf_step<false>(a1p, a0p, E, e1, j, red);
            crf_step<false>(a0p, a1p, E, e2, j, red);
        }

        // ---- partition & gold reduction ----
        float x = a1p[j] * eT;
        float y = gold;
#pragma unroll
        for (int o = 16; o > 0; o >>= 1) {
            x += __shfl_xor_sync(0xffffffffu, x, o);
            y += __shfl_xor_sync(0xffffffffu, y, o);
        }
        __syncthreads();  // alpha/red reuse protection before scratch writes
        if ((j & 31) == 0) { red[j >> 5] = x; red[4 + (j >> 5)] = y; }
        __syncthreads();
        if (j == 0) {
            float sumv = red[0] + red[1] + red[2] + red[3];
            float sumg = red[4] + red[5] + red[6] + red[7];
            double part = (double)le * 0.6931471805599453 + (double)mTE + log((double)sumv);
            g_part[b] = part - (double)sumg;
        }
        __syncthreads();
    }

    // ---- ticket: last CTA reduces all 256 partials ----
    if (j == 0) {
        __threadfence();
        unsigned int t = atomicAdd(&g_ticket, 1u);
        s_last = (t == NCTA - 1) ? 1 : 0;
    }
    __syncthreads();
    if (s_last) {
        double d = __ldcg(&g_part[j]) + __ldcg(&g_part[j + 128]);
#pragma unroll
        for (int o = 16; o > 0; o >>= 1)
            d += __shfl_xor_sync(0xffffffffu, d, o);
        __shared__ double sd[4];
        if ((j & 31) == 0) sd[j >> 5] = d;
        __syncthreads();
        if (j == 0) {
            double tot = sd[0] + sd[1] + sd[2] + sd[3];
            out[0] = (float)(tot * (1.0 / NB));
            g_ticket = 0;  // reset for graph replay
        }
    }
}

extern "C" void kernel_launch(void* const* d_in, const int* in_sizes, int n_in,
                              void* d_out, int out_size) {
    const float* em = (const float*)d_in[0];     // [256,1024,128] f32
    const int* tags = (const int*)d_in[1];       // [256,1024] i32
    const float* trans = (const float*)d_in[2];  // [128,128] f32
    crf_scan_kernel<<<NCTA, 128>>>(em, tags, trans, (float*)d_out);
}

// round 9
// speedup vs baseline: 1.0330x; 1.0330x over previous
#include <cuda_runtime.h>

// CRF loss, linear-domain scan. One CTA (128 threads) per batch row (grid=256,
// 2 CTAs/SM). Thread j owns column j of E=exp(trans) as 64 packed f32x2 regs.
// Alpha ping-pongs in shared memory; ONE __syncthreads per step.
// Renormalization every step for FREE: scale = 2^-exponent(alpha[0]), where
// alpha[0]'s bits come from the first LDS of the dot. Power-of-2 scaling is
// exact; le accumulates the exponent. Final mean fused via atomic ticket.

namespace {
constexpr int TT = 128;
constexpr int SS = 1024;
constexpr int NB = 256;
constexpr int START_TAG = 126;
constexpr int END_TAG = 127;
}

typedef unsigned long long ull;
__device__ double g_part[NB];
__device__ unsigned int g_ticket;

__device__ __forceinline__ ull pack2f(float lo, float hi) {
    ull r;
    asm("mov.b64 %0, {%1, %2};" : "=l"(r) : "f"(lo), "f"(hi));
    return r;
}

// dot of shared alpha[0..127] with this thread's E column; 8 accumulators.
// Also returns the raw bits of alpha[0] (free: low half of first packed load).
__device__ __forceinline__ float dotrow(const float* __restrict__ ar,
                                        const ull* __restrict__ E,
                                        unsigned int& a0bits) {
    ull acc[8];
#pragma unroll
    for (int i = 0; i < 8; i++) acc[i] = 0ull;
    const double2* ap = reinterpret_cast<const double2*>(ar);
    {
        double2 a = ap[0];
        double2 b = ap[1];
        ull a0 = __double_as_longlong(a.x);
        ull a1 = __double_as_longlong(a.y);
        ull b0 = __double_as_longlong(b.x);
        ull b1 = __double_as_longlong(b.y);
        a0bits = (unsigned int)a0;  // bits of alpha[0]
        asm("fma.rn.f32x2 %0, %1, %2, %0;" : "+l"(acc[0]) : "l"(a0), "l"(E[0]));
        asm("fma.rn.f32x2 %0, %1, %2, %0;" : "+l"(acc[1]) : "l"(a1), "l"(E[1]));
        asm("fma.rn.f32x2 %0, %1, %2, %0;" : "+l"(acc[2]) : "l"(b0), "l"(E[2]));
        asm("fma.rn.f32x2 %0, %1, %2, %0;" : "+l"(acc[3]) : "l"(b1), "l"(E[3]));
    }
#pragma unroll
    for (int k = 1; k < 16; k++) {
        double2 a = ap[2 * k];
        double2 b = ap[2 * k + 1];
        ull a0 = __double_as_longlong(a.x);
        ull a1 = __double_as_longlong(a.y);
        ull b0 = __double_as_longlong(b.x);
        ull b1 = __double_as_longlong(b.y);
        asm("fma.rn.f32x2 %0, %1, %2, %0;" : "+l"(acc[(4 * k + 0) & 7]) : "l"(a0), "l"(E[4 * k + 0]));
        asm("fma.rn.f32x2 %0, %1, %2, %0;" : "+l"(acc[(4 * k + 1) & 7]) : "l"(a1), "l"(E[4 * k + 1]));
        asm("fma.rn.f32x2 %0, %1, %2, %0;" : "+l"(acc[(4 * k + 2) & 7]) : "l"(b0), "l"(E[4 * k + 2]));
        asm("fma.rn.f32x2 %0, %1, %2, %0;" : "+l"(acc[(4 * k + 3) & 7]) : "l"(b1), "l"(E[4 * k + 3]));
    }
    asm("add.rn.f32x2 %0, %0, %1;" : "+l"(acc[0]) : "l"(acc[4]));
    asm("add.rn.f32x2 %0, %0, %1;" : "+l"(acc[1]) : "l"(acc[5]));
    asm("add.rn.f32x2 %0, %0, %1;" : "+l"(acc[2]) : "l"(acc[6]));
    asm("add.rn.f32x2 %0, %0, %1;" : "+l"(acc[3]) : "l"(acc[7]));
    asm("add.rn.f32x2 %0, %0, %1;" : "+l"(acc[0]) : "l"(acc[2]));
    asm("add.rn.f32x2 %0, %0, %1;" : "+l"(acc[1]) : "l"(acc[3]));
    asm("add.rn.f32x2 %0, %0, %1;" : "+l"(acc[0]) : "l"(acc[1]));
    float lo, hi;
    asm("mov.b64 {%0, %1}, %2;" : "=f"(lo), "=f"(hi) : "l"(acc[0]));
    return lo + hi;
}

// One scan step. eraw = expf(emission[t][j]). Renorm folded in via exponent
// of alpha[0] (uniform across threads, exact power-of-2).
__device__ __forceinline__ void crf_step(const float* __restrict__ ar,
                                         float* __restrict__ aw,
                                         const ull* __restrict__ E,
                                         float eraw, int j, int& le) {
    unsigned int a0bits;
    float d = dotrow(ar, E, a0bits);
    int ex = (int)(a0bits >> 23) - 127;
    ex = max(-63, min(63, ex));  // handles alpha[0]==0 at t=1 exactly
    le += ex;
    float eadj = __int_as_float(__float_as_int(eraw) - (ex << 23));
    aw[j] = d * eadj;
    __syncthreads();
}

__global__ void __launch_bounds__(128, 2)
crf_scan_kernel(const float* __restrict__ em, const int* __restrict__ tags,
                const float* __restrict__ trans, float* __restrict__ out) {
    const int b = blockIdx.x;
    const int j = threadIdx.x;
    __shared__ __align__(16) float alpha[2][TT];
    __shared__ __align__(16) float red[8];
    __shared__ int s_last;

    const float* emb = em + (size_t)b * SS * TT;
    const int* tg = tags + b * SS;

    // E column j in registers, packed (i, i+1) pairs.
    ull E[64];
#pragma unroll
    for (int k = 0; k < 64; k++) {
        float e0 = __expf(trans[(2 * k) * TT + j]);
        float e1 = __expf(trans[(2 * k + 1) * TT + j]);
        E[k] = pack2f(e0, e1);
    }

    // ---- gold path score ----
    float gold = 0.f;
#pragma unroll
    for (int r = 0; r < SS / TT; r++) {
        int s = r * TT + j;
        int cur = tg[s];
        int prev = (s == 0) ? START_TAG : tg[s - 1];
        gold += emb[s * TT + cur] + trans[prev * TT + cur];
    }
    if (j == 0) gold += trans[tg[SS - 1] * TT + END_TAG];

    // one-time: max of END transition row
    float tE = trans[END_TAG * TT + j];
    {
        float m = tE;
#pragma unroll
        for (int o = 16; o > 0; o >>= 1)
            m = fmaxf(m, __shfl_xor_sync(0xffffffffu, m, o));
        if ((j & 31) == 0) red[j >> 5] = m;
    }
    alpha[0][j] = (j == START_TAG) ? 1.f : 0.f;
    __syncthreads();
    const float mTE = fmaxf(fmaxf(red[0], red[1]), fmaxf(red[2], red[3]));

    // ---- scan, t = 1..1023 ----
    int le = 0;
    float e0 = __expf(emb[1 * TT + j]);
    float e1 = __expf(emb[2 * TT + j]);
    float e2 = __expf(emb[3 * TT + j]);
    float e3 = __expf(emb[4 * TT + j]);
    float* a0p = alpha[0];
    float* a1p = alpha[1];

#pragma unroll 1
    for (int g = 0; g < 254; g++) {
        const int tn = 4 * g + 5;
        float n0 = emb[(tn + 0) * TT + j];
        float n1 = emb[(tn + 1) * TT + j];
        float n2 = emb[(tn + 2) * TT + j];
        float n3 = emb[(tn + 3) * TT + j];
        crf_step(a0p, a1p, E, e0, j, le);
        crf_step(a1p, a0p, E, e1, j, le);
        crf_step(a0p, a1p, E, e2, j, le);
        crf_step(a1p, a0p, E, e3, j, le);
        e0 = __expf(n0); e1 = __expf(n1); e2 = __expf(n2); e3 = __expf(n3);
    }
    // group 254: t = 1017..1020, prefetch tail 1021..1023
    {
        float n0 = emb[1021 * TT + j];
        float n1 = emb[1022 * TT + j];
        float n2 = emb[1023 * TT + j];
        crf_step(a0p, a1p, E, e0, j, le);
        crf_step(a1p, a0p, E, e1, j, le);
        crf_step(a0p, a1p, E, e2, j, le);
        crf_step(a1p, a0p, E, e3, j, le);
        e0 = __expf(n0); e1 = __expf(n1); e2 = __expf(n2);
    }
    // tail: t = 1021..1023 (final alpha ends in alpha[1])
    crf_step(a0p, a1p, E, e0, j, le);
    crf_step(a1p, a0p, E, e1, j, le);
    crf_step(a0p, a1p, E, e2, j, le);

    // ---- partition = le*ln2 + mTE + log(sum_j alpha[j]*exp(tE_j - mTE)) ----
    float v = a1p[j] * __expf(tE - mTE);
    float x = v, y = gold;
#pragma unroll
    for (int o = 16; o > 0; o >>= 1) {
        x += __shfl_xor_sync(0xffffffffu, x, o);
        y += __shfl_xor_sync(0xffffffffu, y, o);
    }
    if ((j & 31) == 0) { red[j >> 5] = x; red[4 + (j >> 5)] = y; }
    __syncthreads();
    if (j == 0) {
        float sumv = red[0] + red[1] + red[2] + red[3];
        float sumg = red[4] + red[5] + red[6] + red[7];
        double part = (double)le * 0.6931471805599453 + (double)mTE + log((double)sumv);
        g_part[b] = part - (double)sumg;
        __threadfence();
        unsigned int t = atomicAdd(&g_ticket, 1u);
        s_last = (t == NB - 1) ? 1 : 0;
    }
    __syncthreads();

    // ---- last CTA reduces the 256 partials and writes the mean ----
    if (s_last) {
        double d = __ldcg(&g_part[j]) + __ldcg(&g_part[j + 128]);
#pragma unroll
        for (int o = 16; o > 0; o >>= 1)
            d += __shfl_xor_sync(0xffffffffu, d, o);
        __shared__ double sd[4];
        if ((j & 31) == 0) sd[j >> 5] = d;
        __syncthreads();
        if (j == 0) {
            double tot = sd[0] + sd[1] + sd[2] + sd[3];
            out[0] = (float)(tot * (1.0 / NB));
            g_ticket = 0;  // reset for graph replay
        }
    }
}

extern "C" void kernel_launch(void* const* d_in, const int* in_sizes, int n_in,
                              void* d_out, int out_size) {
    const float* em = (const float*)d_in[0];     // [256,1024,128] f32
    const int* tags = (const int*)d_in[1];       // [256,1024] i32
    const float* trans = (const float*)d_in[2];  // [128,128] f32
    crf_scan_kernel<<<NB, 128>>>(em, tags, trans, (float*)d_out);
}

// round 10
// speedup vs baseline: 1.3132x; 1.2713x over previous
#include <cuda_runtime.h>

// CRF loss, linear-domain scan — R3 champion shape + pipelined LDS + fused finish.
// One CTA (128 threads) per batch row (grid=256, 2 CTAs/SM). Thread j owns
// column j of E=exp(trans) as 64 packed f32x2 regs. Alpha ping-pongs in shared
// memory; ONE __syncthreads per step. Deferred power-of-2 renorm every 4 steps
// (redux.sync.max.s32 on non-negative values). Final mean via atomic ticket.

namespace {
constexpr int TT = 128;
constexpr int SS = 1024;
constexpr int NB = 256;
constexpr int START_TAG = 126;
constexpr int END_TAG = 127;
}

typedef unsigned long long ull;
__device__ double g_part[NB];
__device__ unsigned int g_ticket;

__device__ __forceinline__ ull pack2f(float lo, float hi) {
    ull r;
    asm("mov.b64 %0, {%1, %2};" : "=l"(r) : "f"(lo), "f"(hi));
    return r;
}

// dot of shared alpha[0..127] with this thread's E column.
// Software-pipelined: 8 batches of 4x LDS.128, loaded 2 batches ahead,
// consumed as 8 FFMA2 per batch into 8 accumulators.
__device__ __forceinline__ float dotrow(const float* __restrict__ ar,
                                        const ull* __restrict__ E) {
    const double2* ap = reinterpret_cast<const double2*>(ar);
    ull acc[8];
#pragma unroll
    for (int i = 0; i < 8; i++) acc[i] = 0ull;
    double2 buf[3][4];
#pragma unroll
    for (int i = 0; i < 4; i++) buf[0][i] = ap[i];
#pragma unroll
    for (int i = 0; i < 4; i++) buf[1][i] = ap[4 + i];
#pragma unroll
    for (int b = 0; b < 8; b++) {
        if (b < 6) {
#pragma unroll
            for (int i = 0; i < 4; i++)
                buf[(b + 2) % 3][i] = ap[4 * (b + 2) + i];
        }
        const double2* cb = buf[b % 3];
#pragma unroll
        for (int i = 0; i < 4; i++) {
            ull lo = __double_as_longlong(cb[i].x);
            ull hi = __double_as_longlong(cb[i].y);
            asm("fma.rn.f32x2 %0, %1, %2, %0;"
                : "+l"(acc[2 * i]) : "l"(lo), "l"(E[8 * b + 2 * i]));
            asm("fma.rn.f32x2 %0, %1, %2, %0;"
                : "+l"(acc[2 * i + 1]) : "l"(hi), "l"(E[8 * b + 2 * i + 1]));
        }
    }
    asm("add.rn.f32x2 %0, %0, %1;" : "+l"(acc[0]) : "l"(acc[4]));
    asm("add.rn.f32x2 %0, %0, %1;" : "+l"(acc[1]) : "l"(acc[5]));
    asm("add.rn.f32x2 %0, %0, %1;" : "+l"(acc[2]) : "l"(acc[6]));
    asm("add.rn.f32x2 %0, %0, %1;" : "+l"(acc[3]) : "l"(acc[7]));
    asm("add.rn.f32x2 %0, %0, %1;" : "+l"(acc[0]) : "l"(acc[2]));
    asm("add.rn.f32x2 %0, %0, %1;" : "+l"(acc[1]) : "l"(acc[3]));
    asm("add.rn.f32x2 %0, %0, %1;" : "+l"(acc[0]) : "l"(acc[1]));
    float lo, hi;
    asm("mov.b64 {%0, %1}, %2;" : "=f"(lo), "=f"(hi) : "l"(acc[0]));
    return lo + hi;
}

template <bool REN>
__device__ __forceinline__ void crf_step(const float* __restrict__ ar,
                                         float* __restrict__ aw,
                                         const ull* __restrict__ E,
                                         float expem, int j, float* red) {
    float v = dotrow(ar, E) * expem;
    aw[j] = v;
    if (REN) {
        int m;  // v >= 0: fp max == s32 max on bit patterns
        asm volatile("redux.sync.max.s32 %0, %1, 0xffffffff;"
                     : "=r"(m) : "r"(__float_as_int(v)));
        if ((j & 31) == 0) red[j >> 5] = __int_as_float(m);
    }
    __syncthreads();
}

__device__ __forceinline__ void consume_max(const float* red, int& le, float& sc) {
    float4 r4 = *reinterpret_cast<const float4*>(red);
    float mm = fmaxf(fmaxf(r4.x, r4.y), fmaxf(r4.z, r4.w));
    int ex = (__float_as_int(mm) >> 23) - 127;
    le += ex;
    sc = __int_as_float((127 - ex) << 23);
}

__global__ void __launch_bounds__(128, 2)
crf_scan_kernel(const float* __restrict__ em, const int* __restrict__ tags,
                const float* __restrict__ trans, float* __restrict__ out) {
    const int b = blockIdx.x;
    const int j = threadIdx.x;
    __shared__ __align__(16) float alpha[2][TT];
    __shared__ __align__(16) float red[8];
    __shared__ int s_last;

    const float* emb = em + (size_t)b * SS * TT;
    const int* tg = tags + b * SS;

    // E column j in registers, packed (i, i+1) pairs.
    ull E[64];
#pragma unroll
    for (int k = 0; k < 64; k++) {
        float e0 = __expf(trans[(2 * k) * TT + j]);
        float e1 = __expf(trans[(2 * k + 1) * TT + j]);
        E[k] = pack2f(e0, e1);
    }

    // ---- gold path score ----
    float gold = 0.f;
#pragma unroll
    for (int r = 0; r < SS / TT; r++) {
        int s = r * TT + j;
        int cur = tg[s];
        int prev = (s == 0) ? START_TAG : tg[s - 1];
        gold += emb[s * TT + cur] + trans[prev * TT + cur];
    }
    if (j == 0) gold += trans[tg[SS - 1] * TT + END_TAG];

    // one-time: max of END transition row
    float tE = trans[END_TAG * TT + j];
    {
        float m = tE;
#pragma unroll
        for (int o = 16; o > 0; o >>= 1)
            m = fmaxf(m, __shfl_xor_sync(0xffffffffu, m, o));
        if ((j & 31) == 0) red[j >> 5] = m;
    }
    __syncthreads();
    const float mTE = fmaxf(fmaxf(red[0], red[1]), fmaxf(red[2], red[3]));
    __syncthreads();
    if (j < 4) red[j] = 1.0f;  // first group: ex=0, sc=1
    alpha[0][j] = (j == START_TAG) ? 1.f : 0.f;
    __syncthreads();

    // ---- scan, t = 1..1023 ----
    int le = 0;
    float b0 = emb[1 * TT + j];
    float b1 = emb[2 * TT + j];
    float b2 = emb[3 * TT + j];
    float b3 = emb[4 * TT + j];
    float* a0p = alpha[0];
    float* a1p = alpha[1];

#pragma unroll 1
    for (int g = 0; g < 254; g++) {
        float sc;
        consume_max(red, le, sc);
        float e0 = __expf(b0) * sc;
        float e1 = __expf(b1);
        float e2 = __expf(b2);
        float e3 = __expf(b3);
        const int tn = 4 * g + 5;
        float n0 = emb[(tn + 0) * TT + j];
        float n1 = emb[(tn + 1) * TT + j];
        float n2 = emb[(tn + 2) * TT + j];
        float n3 = emb[(tn + 3) * TT + j];
        crf_step<false>(a0p, a1p, E, e0, j, red);
        crf_step<false>(a1p, a0p, E, e1, j, red);
        crf_step<false>(a0p, a1p, E, e2, j, red);
        crf_step<true >(a1p, a0p, E, e3, j, red);
        b0 = n0; b1 = n1; b2 = n2; b3 = n3;
    }
    // group 255: t = 1017..1020, prefetch tail
    {
        float sc;
        consume_max(red, le, sc);
        float e0 = __expf(b0) * sc;
        float e1 = __expf(b1);
        float e2 = __expf(b2);
        float e3 = __expf(b3);
        float n0 = emb[1021 * TT + j];
        float n1 = emb[1022 * TT + j];
        float n2 = emb[1023 * TT + j];
        crf_step<false>(a0p, a1p, E, e0, j, red);
        crf_step<false>(a1p, a0p, E, e1, j, red);
        crf_step<false>(a0p, a1p, E, e2, j, red);
        crf_step<true >(a1p, a0p, E, e3, j, red);
        b0 = n0; b1 = n1; b2 = n2;
    }
    // tail: t = 1021..1023 (final alpha in buffer 1)
    {
        float sc;
        consume_max(red, le, sc);
        float e0 = __expf(b0) * sc;
        float e1 = __expf(b1);
        float e2 = __expf(b2);
        crf_step<false>(a0p, a1p, E, e0, j, red);
        crf_step<false>(a1p, a0p, E, e1, j, red);
        crf_step<false>(a0p, a1p, E, e2, j, red);
    }

    // ---- partition & gold reduction ----
    float v = a1p[j] * __expf(tE - mTE);
    float x = v, y = gold;
#pragma unroll
    for (int o = 16; o > 0; o >>= 1) {
        x += __shfl_xor_sync(0xffffffffu, x, o);
        y += __shfl_xor_sync(0xffffffffu, y, o);
    }
    if ((j & 31) == 0) { red[j >> 5] = x; red[4 + (j >> 5)] = y; }
    __syncthreads();
    if (j == 0) {
        float sumv = red[0] + red[1] + red[2] + red[3];
        float sumg = red[4] + red[5] + red[6] + red[7];
        double part = (double)le * 0.6931471805599453 + (double)mTE + log((double)sumv);
        g_part[b] = part - (double)sumg;
        __threadfence();
        unsigned int t = atomicAdd(&g_ticket, 1u);
        s_last = (t == NB - 1) ? 1 : 0;
    }
    __syncthreads();

    // ---- last CTA reduces the 256 partials and writes the mean ----
    if (s_last) {
        double d = __ldcg(&g_part[j]) + __ldcg(&g_part[j + 128]);
#pragma unroll
        for (int o = 16; o > 0; o >>= 1)
            d += __shfl_xor_sync(0xffffffffu, d, o);
        __shared__ double sd[4];
        if ((j & 31) == 0) sd[j >> 5] = d;
        __syncthreads();
        if (j == 0) {
            double tot = sd[0] + sd[1] + sd[2] + sd[3];
            out[0] = (float)(tot * (1.0 / NB));
            g_ticket = 0;  // reset for graph replay
        }
    }
}

extern "C" void kernel_launch(void* const* d_in, const int* in_sizes, int n_in,
                              void* d_out, int out_size) {
    const float* em = (const float*)d_in[0];     // [256,1024,128] f32
    const int* tags = (const int*)d_in[1];       // [256,1024] i32
    const float* trans = (const float*)d_in[2];  // [128,128] f32
    crf_scan_kernel<<<NB, 128>>>(em, tags, trans, (float*)d_out);
}

// round 11
// speedup vs baseline: 1.3219x; 1.0066x over previous
#include <cuda_runtime.h>

// CRF loss, linear-domain scan — forward/backward split for load balance.
// grid = 296 (2 CTAs on every SM): bids 0..255 run FORWARD scans (t=1..896)
// of row bid; bids 256..295 run BACKWARD scans (t=1023..897) of rows
// bid-256, bid-216, ... (stride 40). Join per row: Z = sum_j A896[j]*B896[j].
// Step kernel identical to the R3 champion: thread j owns E column (fwd) or
// E row (bwd) as 64 packed f32x2 regs; alpha ping-pongs in smem; ONE
// __syncthreads per step; deferred power-of-2 renorm every 4 steps.

namespace {
constexpr int TT = 128;
constexpr int SS = 1024;
constexpr int NB = 256;
constexpr int NBWD = 40;
constexpr int GRID = NB + NBWD;  // 296 = 2 * 148
constexpr int FWD_STEPS = 896;   // fwd covers t = 1..896
constexpr int BWD_SCALED = 126;  // bwd scaled steps: t = 1022..897
constexpr int START_TAG = 126;
constexpr int END_TAG = 127;
}

typedef unsigned long long ull;
__device__ float g_avec[NB][TT];
__device__ float g_bvec[NB][TT];
__device__ int g_lea[NB];
__device__ int g_leb[NB];
__device__ float g_gold[NB];
__device__ double g_part[NB];
__device__ unsigned int g_cnt[NB];
__device__ unsigned int g_ticket;

__device__ __forceinline__ ull pack2f(float lo, float hi) {
    ull r;
    asm("mov.b64 %0, {%1, %2};" : "=l"(r) : "f"(lo), "f"(hi));
    return r;
}

// dot of shared vec[0..127] with this thread's E pairs; 8 accumulators (R3).
__device__ __forceinline__ float dotrow(const float* __restrict__ ar,
                                        const ull* __restrict__ E) {
    ull acc[8];
#pragma unroll
    for (int i = 0; i < 8; i++) acc[i] = 0ull;
    const double2* ap = reinterpret_cast<const double2*>(ar);
#pragma unroll
    for (int k = 0; k < 16; k++) {
        double2 a = ap[2 * k];
        double2 b = ap[2 * k + 1];
        ull a0 = __double_as_longlong(a.x);
        ull a1 = __double_as_longlong(a.y);
        ull b0 = __double_as_longlong(b.x);
        ull b1 = __double_as_longlong(b.y);
        asm("fma.rn.f32x2 %0, %1, %2, %0;" : "+l"(acc[(4 * k + 0) & 7]) : "l"(a0), "l"(E[4 * k + 0]));
        asm("fma.rn.f32x2 %0, %1, %2, %0;" : "+l"(acc[(4 * k + 1) & 7]) : "l"(a1), "l"(E[4 * k + 1]));
        asm("fma.rn.f32x2 %0, %1, %2, %0;" : "+l"(acc[(4 * k + 2) & 7]) : "l"(b0), "l"(E[4 * k + 2]));
        asm("fma.rn.f32x2 %0, %1, %2, %0;" : "+l"(acc[(4 * k + 3) & 7]) : "l"(b1), "l"(E[4 * k + 3]));
    }
    asm("add.rn.f32x2 %0, %0, %1;" : "+l"(acc[0]) : "l"(acc[4]));
    asm("add.rn.f32x2 %0, %0, %1;" : "+l"(acc[1]) : "l"(acc[5]));
    asm("add.rn.f32x2 %0, %0, %1;" : "+l"(acc[2]) : "l"(acc[6]));
    asm("add.rn.f32x2 %0, %0, %1;" : "+l"(acc[3]) : "l"(acc[7]));
    asm("add.rn.f32x2 %0, %0, %1;" : "+l"(acc[0]) : "l"(acc[2]));
    asm("add.rn.f32x2 %0, %0, %1;" : "+l"(acc[1]) : "l"(acc[3]));
    asm("add.rn.f32x2 %0, %0, %1;" : "+l"(acc[0]) : "l"(acc[1]));
    float lo, hi;
    asm("mov.b64 {%0, %1}, %2;" : "=f"(lo), "=f"(hi) : "l"(acc[0]));
    return lo + hi;
}

template <bool REN>
__device__ __forceinline__ void crf_step(const float* __restrict__ ar,
                                         float* __restrict__ aw,
                                         const ull* __restrict__ E,
                                         float expem, int j, float* red) {
    float v = dotrow(ar, E) * expem;
    aw[j] = v;
    if (REN) {
        int m;  // v >= 0: fp max == s32 max on bit patterns
        asm volatile("redux.sync.max.s32 %0, %1, 0xffffffff;"
                     : "=r"(m) : "r"(__float_as_int(v)));
        if ((j & 31) == 0) red[j >> 5] = __int_as_float(m);
    }
    __syncthreads();
}

__device__ __forceinline__ void consume_max(const float* red, int& le, float& sc) {
    float4 r4 = *reinterpret_cast<const float4*>(red);
    float mm = fmaxf(fmaxf(r4.x, r4.y), fmaxf(r4.z, r4.w));
    int ex = (__float_as_int(mm) >> 23) - 127;
    le += ex;
    sc = __int_as_float((127 - ex) << 23);
}

// Generic linear scan: nsteps matvec+scale steps. e for step s lives at
// e0ptr[s*strideElems]. Returns pointer to the smem buffer holding the result.
__device__ __forceinline__ float* scan_lin(float (*alpha)[TT], const ull* E,
                                           const float* e0ptr, int strideElems,
                                           int nsteps, int j, float* red, int& le) {
    float* ra = alpha[0];
    float* wa = alpha[1];
    float b0 = e0ptr[0];
    float b1 = e0ptr[strideElems];
    float b2 = e0ptr[2 * strideElems];
    float b3 = e0ptr[3 * strideElems];
    const float* nx = e0ptr + 4 * strideElems;
    int done = 0;
#pragma unroll 1
    for (; done + 8 <= nsteps; done += 4) {
        float sc;
        consume_max(red, le, sc);
        float e0 = __expf(b0) * sc;
        float e1 = __expf(b1);
        float e2 = __expf(b2);
        float e3 = __expf(b3);
        float n0 = nx[0];
        float n1 = nx[strideElems];
        float n2 = nx[2 * strideElems];
        float n3 = nx[3 * strideElems];
        nx += 4 * strideElems;
        crf_step<false>(ra, wa, E, e0, j, red); { float* t = ra; ra = wa; wa = t; }
        crf_step<false>(ra, wa, E, e1, j, red); { float* t = ra; ra = wa; wa = t; }
        crf_step<false>(ra, wa, E, e2, j, red); { float* t = ra; ra = wa; wa = t; }
        crf_step<true >(ra, wa, E, e3, j, red); { float* t = ra; ra = wa; wa = t; }
        b0 = n0; b1 = n1; b2 = n2; b3 = n3;
    }
    // buffered group (steps done..done+3) + prefetch of 0..3 tail emissions
    const int rem = nsteps - done - 4;  // 0..3
    float m0 = 0.f, m1 = 0.f, m2 = 0.f;
    if (rem > 0) m0 = nx[0];
    if (rem > 1) m1 = nx[strideElems];
    if (rem > 2) m2 = nx[2 * strideElems];
    {
        float sc;
        consume_max(red, le, sc);
        float e0 = __expf(b0) * sc;
        float e1 = __expf(b1);
        float e2 = __expf(b2);
        float e3 = __expf(b3);
        crf_step<false>(ra, wa, E, e0, j, red); { float* t = ra; ra = wa; wa = t; }
        crf_step<false>(ra, wa, E, e1, j, red); { float* t = ra; ra = wa; wa = t; }
        crf_step<false>(ra, wa, E, e2, j, red); { float* t = ra; ra = wa; wa = t; }
        crf_step<true >(ra, wa, E, e3, j, red); { float* t = ra; ra = wa; wa = t; }
    }
    if (rem > 0) {
        float sc;
        consume_max(red, le, sc);
        crf_step<false>(ra, wa, E, __expf(m0) * sc, j, red); { float* t = ra; ra = wa; wa = t; }
        if (rem > 1) { crf_step<false>(ra, wa, E, __expf(m1), j, red); float* t = ra; ra = wa; wa = t; }
        if (rem > 2) { crf_step<false>(ra, wa, E, __expf(m2), j, red); float* t = ra; ra = wa; wa = t; }
    }
    return ra;
}

__global__ void __launch_bounds__(128, 2)
crf_kernel(const float* __restrict__ em, const int* __restrict__ tags,
           const float* __restrict__ trans, float* __restrict__ out) {
    const int bid = blockIdx.x;
    const int j = threadIdx.x;
    __shared__ __align__(16) float alpha[2][TT];
    __shared__ __align__(16) float red[8];
    __shared__ int sjoin, sfinal;

    const bool isFwd = (bid < NB);

    // E pairs: fwd thread j owns column j (pairs over i); bwd thread j owns
    // row j of E (pairs over k) for the transposed matvec.
    ull E[64];
    if (isFwd) {
#pragma unroll
        for (int k = 0; k < 64; k++)
            E[k] = pack2f(__expf(trans[(2 * k) * TT + j]),
                          __expf(trans[(2 * k + 1) * TT + j]));
    } else {
#pragma unroll
        for (int k = 0; k < 64; k++)
            E[k] = pack2f(__expf(trans[j * TT + 2 * k]),
                          __expf(trans[j * TT + 2 * k + 1]));
    }

    // one-time: max of END transition row
    float tE = trans[END_TAG * TT + j];
    {
        float m = tE;
#pragma unroll
        for (int o = 16; o > 0; o >>= 1)
            m = fmaxf(m, __shfl_xor_sync(0xffffffffu, m, o));
        if ((j & 31) == 0) red[j >> 5] = m;
    }
    __syncthreads();
    const float mTE = fmaxf(fmaxf(red[0], red[1]), fmaxf(red[2], red[3]));
    __syncthreads();

    if (isFwd) {
        const int r = bid;
        const float* emb = em + (size_t)r * SS * TT;
        const int* tg = tags + r * SS;

        // gold path score (full row)
        float gold = 0.f;
#pragma unroll
        for (int q = 0; q < SS / TT; q++) {
            int s = q * TT + j;
            int cur = tg[s];
            int prev = (s == 0) ? START_TAG : tg[s - 1];
            gold += emb[s * TT + cur] + trans[prev * TT + cur];
        }
        if (j == 0) gold += trans[tg[SS - 1] * TT + END_TAG];

        if (j < 4) red[j] = 1.0f;
        alpha[0][j] = (j == START_TAG) ? 1.f : 0.f;
        __syncthreads();

        int le = 0;
        float* ra = scan_lin(alpha, E, emb + TT + j, TT, FWD_STEPS, j, red, le);
        g_avec[r][j] = ra[j];

        float y = gold;
#pragma unroll
        for (int o = 16; o > 0; o >>= 1)
            y += __shfl_xor_sync(0xffffffffu, y, o);
        if ((j & 31) == 0) red[4 + (j >> 5)] = y;
        __syncthreads();
        if (j == 0) {
            g_gold[r] = red[4] + red[5] + red[6] + red[7];
            g_lea[r] = le;
        }
        // ---- join ----
        __threadfence();
        __syncthreads();
        if (j == 0) sjoin = (atomicAdd(&g_cnt[r], 1u) == 1u) ? 1 : 0;
        __syncthreads();
        if (sjoin) {
            __threadfence();
            float p = __ldcg(&g_avec[r][j]) * __ldcg(&g_bvec[r][j]);
#pragma unroll
            for (int o = 16; o > 0; o >>= 1)
                p += __shfl_xor_sync(0xffffffffu, p, o);
            if ((j & 31) == 0) red[j >> 5] = p;
            __syncthreads();
            if (j == 0) {
                float s = red[0] + red[1] + red[2] + red[3];
                int lt = __ldcg(&g_lea[r]) + __ldcg(&g_leb[r]);
                double part = (double)lt * 0.6931471805599453 + (double)mTE +
                              log((double)s) - (double)__ldcg(&g_gold[r]);
                g_part[r] = part;
                g_cnt[r] = 0;
                __threadfence();
                sfinal = (atomicAdd(&g_ticket, 1u) == NB - 1) ? 1 : 0;
            }
            __syncthreads();
            if (sfinal) {
                __threadfence();
                double d = __ldcg(&g_part[j]) + __ldcg(&g_part[j + 128]);
#pragma unroll
                for (int o = 16; o > 0; o >>= 1)
                    d += __shfl_xor_sync(0xffffffffu, d, o);
                __shared__ double sd[4];
                if ((j & 31) == 0) sd[j >> 5] = d;
                __syncthreads();
                if (j == 0) {
                    out[0] = (float)((sd[0] + sd[1] + sd[2] + sd[3]) * (1.0 / NB));
                    g_ticket = 0;
                }
            }
        }
    } else {
        // ---- backward CTA: rows bid-256, +40, ... ----
#pragma unroll 1
        for (int r = bid - NB; r < NB; r += NBWD) {
            const float* emb = em + (size_t)r * SS * TT;
            __syncthreads();
            if (j < 4) red[j] = 1.0f;
            // B~_1023[j] = e_1023[j] * exp(tE[j] - mTE)
            alpha[0][j] = __expf(emb[1023 * TT + j]) * __expf(tE - mTE);
            __syncthreads();

            int le = 0;
            float* ra = scan_lin(alpha, E, emb + 1022 * TT + j, -TT,
                                 BWD_SCALED, j, red, le);
            // final unscaled matvec: B_896[j] = sum_k E[j,k] * B~_897[k]
            float v = dotrow(ra, E);
            g_bvec[r][j] = v;
            if (j == 0) g_leb[r] = le;

            // ---- join ----
            __threadfence();
            __syncthreads();
            if (j == 0) sjoin = (atomicAdd(&g_cnt[r], 1u) == 1u) ? 1 : 0;
            __syncthreads();
            if (sjoin) {
                __threadfence();
                float p = __ldcg(&g_avec[r][j]) * __ldcg(&g_bvec[r][j]);
#pragma unroll
                for (int o = 16; o > 0; o >>= 1)
                    p += __shfl_xor_sync(0xffffffffu, p, o);
                if ((j & 31) == 0) red[j >> 5] = p;
                __syncthreads();
                if (j == 0) {
                    float s = red[0] + red[1] + red[2] + red[3];
                    int lt = __ldcg(&g_lea[r]) + __ldcg(&g_leb[r]);
                    double part = (double)lt * 0.6931471805599453 + (double)mTE +
                                  log((double)s) - (double)__ldcg(&g_gold[r]);
                    g_part[r] = part;
                    g_cnt[r] = 0;
                    __threadfence();
                    sfinal = (atomicAdd(&g_ticket, 1u) == NB - 1) ? 1 : 0;
                }
                __syncthreads();
                if (sfinal) {
                    __threadfence();
                    double d = __ldcg(&g_part[j]) + __ldcg(&g_part[j + 128]);
#pragma unroll
                    for (int o = 16; o > 0; o >>= 1)
                        d += __shfl_xor_sync(0xffffffffu, d, o);
                    __shared__ double sd[4];
                    if ((j & 31) == 0) sd[j >> 5] = d;
                    __syncthreads();
                    if (j == 0) {
                        out[0] = (float)((sd[0] + sd[1] + sd[2] + sd[3]) * (1.0 / NB));
                        g_ticket = 0;
                    }
                }
                __syncthreads();
            }
        }
    }
}

extern "C" void kernel_launch(void* const* d_in, const int* in_sizes, int n_in,
                              void* d_out, int out_size) {
    const float* em = (const float*)d_in[0];     // [256,1024,128] f32
    const int* tags = (const int*)d_in[1];       // [256,1024] i32
    const float* trans = (const float*)d_in[2];  // [128,128] f32
    crf_kernel<<<GRID, 128>>>(em, tags, trans, (float*)d_out);
}

// round 12
// speedup vs baseline: 1.4083x; 1.0654x over previous
#include <cuda_runtime.h>

// CRF loss, linear-domain scan — fwd/bwd split with R3-champion step bodies.
// grid = 296 (2 CTAs/SM): bids 0..255 FORWARD scan rows (t=1..896, 224 groups,
// compile-time offsets); bids 256..295 BACKWARD scan rows bid-256+40k
// (t=1023 init, 126 scaled steps down to t=897, final plain matvec).
// Join per row: Z = sum_j A896[j]*B896[j], via per-row atomic ticket.
// Thread j owns E column (fwd) / E row (bwd) as 64 packed f32x2 regs.
// ONE __syncthreads per step; deferred power-of-2 renorm every 4 steps.

namespace {
constexpr int TT = 128;
constexpr int SS = 1024;
constexpr int NB = 256;
constexpr int NBWD = 40;
constexpr int GRID = NB + NBWD;  // 296 = 2 * 148
constexpr int START_TAG = 126;
constexpr int END_TAG = 127;
}

typedef unsigned long long ull;
__device__ float g_avec[NB][TT];
__device__ float g_bvec[NB][TT];
__device__ int g_lea[NB];
__device__ int g_leb[NB];
__device__ float g_gold[NB];
__device__ double g_part[NB];
__device__ unsigned int g_cnt[NB];
__device__ unsigned int g_ticket;

__device__ __forceinline__ ull pack2f(float lo, float hi) {
    ull r;
    asm("mov.b64 %0, {%1, %2};" : "=l"(r) : "f"(lo), "f"(hi));
    return r;
}

// dot of shared vec[0..127] with this thread's E pairs; 8 accumulators (R3).
__device__ __forceinline__ float dotrow(const float* __restrict__ ar,
                                        const ull* __restrict__ E) {
    ull acc[8];
#pragma unroll
    for (int i = 0; i < 8; i++) acc[i] = 0ull;
    const double2* ap = reinterpret_cast<const double2*>(ar);
#pragma unroll
    for (int k = 0; k < 16; k++) {
        double2 a = ap[2 * k];
        double2 b = ap[2 * k + 1];
        ull a0 = __double_as_longlong(a.x);
        ull a1 = __double_as_longlong(a.y);
        ull b0 = __double_as_longlong(b.x);
        ull b1 = __double_as_longlong(b.y);
        asm("fma.rn.f32x2 %0, %1, %2, %0;" : "+l"(acc[(4 * k + 0) & 7]) : "l"(a0), "l"(E[4 * k + 0]));
        asm("fma.rn.f32x2 %0, %1, %2, %0;" : "+l"(acc[(4 * k + 1) & 7]) : "l"(a1), "l"(E[4 * k + 1]));
        asm("fma.rn.f32x2 %0, %1, %2, %0;" : "+l"(acc[(4 * k + 2) & 7]) : "l"(b0), "l"(E[4 * k + 2]));
        asm("fma.rn.f32x2 %0, %1, %2, %0;" : "+l"(acc[(4 * k + 3) & 7]) : "l"(b1), "l"(E[4 * k + 3]));
    }
    asm("add.rn.f32x2 %0, %0, %1;" : "+l"(acc[0]) : "l"(acc[4]));
    asm("add.rn.f32x2 %0, %0, %1;" : "+l"(acc[1]) : "l"(acc[5]));
    asm("add.rn.f32x2 %0, %0, %1;" : "+l"(acc[2]) : "l"(acc[6]));
    asm("add.rn.f32x2 %0, %0, %1;" : "+l"(acc[3]) : "l"(acc[7]));
    asm("add.rn.f32x2 %0, %0, %1;" : "+l"(acc[0]) : "l"(acc[2]));
    asm("add.rn.f32x2 %0, %0, %1;" : "+l"(acc[1]) : "l"(acc[3]));
    asm("add.rn.f32x2 %0, %0, %1;" : "+l"(acc[0]) : "l"(acc[1]));
    float lo, hi;
    asm("mov.b64 {%0, %1}, %2;" : "=f"(lo), "=f"(hi) : "l"(acc[0]));
    return lo + hi;
}

template <bool REN>
__device__ __forceinline__ void crf_step(const float* __restrict__ ar,
                                         float* __restrict__ aw,
                                         const ull* __restrict__ E,
                                         float expem, int j, float* red) {
    float v = dotrow(ar, E) * expem;
    aw[j] = v;
    if (REN) {
        int m;  // v >= 0: fp max == s32 max on bit patterns
        asm volatile("redux.sync.max.s32 %0, %1, 0xffffffff;"
                     : "=r"(m) : "r"(__float_as_int(v)));
        if ((j & 31) == 0) red[j >> 5] = __int_as_float(m);
    }
    __syncthreads();
}

__device__ __forceinline__ void consume_max(const float* red, int& le, float& sc) {
    float4 r4 = *reinterpret_cast<const float4*>(red);
    float mm = fmaxf(fmaxf(r4.x, r4.y), fmaxf(r4.z, r4.w));
    int ex = (__float_as_int(mm) >> 23) - 127;
    le += ex;
    sc = __int_as_float((127 - ex) << 23);
}

// Per-row join + final reduction (both sides run this; second arriver reduces)
__device__ __forceinline__ void join_row(int r, float mTE, int le_local, int j,
                                         float* red, float* out) {
    __shared__ int sjoin, sfinal;
    __threadfence();
    __syncthreads();
    if (j == 0) sjoin = (atomicAdd(&g_cnt[r], 1u) == 1u) ? 1 : 0;
    __syncthreads();
    if (!sjoin) return;
    __threadfence();
    float p = __ldcg(&g_avec[r][j]) * __ldcg(&g_bvec[r][j]);
#pragma unroll
    for (int o = 16; o > 0; o >>= 1)
        p += __shfl_xor_sync(0xffffffffu, p, o);
    if ((j & 31) == 0) red[j >> 5] = p;
    __syncthreads();
    if (j == 0) {
        float s = red[0] + red[1] + red[2] + red[3];
        int lt = __ldcg(&g_lea[r]) + __ldcg(&g_leb[r]);
        double part = (double)lt * 0.6931471805599453 + (double)mTE +
                      log((double)s) - (double)__ldcg(&g_gold[r]);
        g_part[r] = part;
        g_cnt[r] = 0;
        __threadfence();
        sfinal = (atomicAdd(&g_ticket, 1u) == NB - 1) ? 1 : 0;
    }
    __syncthreads();
    if (sfinal) {
        __threadfence();
        double d = __ldcg(&g_part[j]) + __ldcg(&g_part[j + 128]);
#pragma unroll
        for (int o = 16; o > 0; o >>= 1)
            d += __shfl_xor_sync(0xffffffffu, d, o);
        __shared__ double sd[4];
        if ((j & 31) == 0) sd[j >> 5] = d;
        __syncthreads();
        if (j == 0) {
            out[0] = (float)((sd[0] + sd[1] + sd[2] + sd[3]) * (1.0 / NB));
            g_ticket = 0;  // reset for graph replay
        }
    }
    __syncthreads();
}

__global__ void __launch_bounds__(128, 2)
crf_kernel(const float* __restrict__ em, const int* __restrict__ tags,
           const float* __restrict__ trans, float* __restrict__ out) {
    const int bid = blockIdx.x;
    const int j = threadIdx.x;
    __shared__ __align__(16) float alpha[2][TT];
    __shared__ __align__(16) float red[8];

    const bool isFwd = (bid < NB);

    // E pairs: fwd thread j owns column j (pairs over i); bwd thread j owns
    // row j (pairs over k) for the transposed matvec.
    ull E[64];
    if (isFwd) {
#pragma unroll
        for (int k = 0; k < 64; k++)
            E[k] = pack2f(__expf(trans[(2 * k) * TT + j]),
                          __expf(trans[(2 * k + 1) * TT + j]));
    } else {
#pragma unroll
        for (int k = 0; k < 64; k++)
            E[k] = pack2f(__expf(trans[j * TT + 2 * k]),
                          __expf(trans[j * TT + 2 * k + 1]));
    }

    // one-time: max of END transition row
    float tE = trans[END_TAG * TT + j];
    {
        float m = tE;
#pragma unroll
        for (int o = 16; o > 0; o >>= 1)
            m = fmaxf(m, __shfl_xor_sync(0xffffffffu, m, o));
        if ((j & 31) == 0) red[j >> 5] = m;
    }
    __syncthreads();
    const float mTE = fmaxf(fmaxf(red[0], red[1]), fmaxf(red[2], red[3]));
    __syncthreads();

    if (isFwd) {
        // ================= FORWARD: row bid, t = 1..896 =================
        const int r = bid;
        const float* emb = em + (size_t)r * SS * TT;
        const int* tg = tags + r * SS;

        // gold path score (full row)
        float gold = 0.f;
#pragma unroll
        for (int q = 0; q < SS / TT; q++) {
            int s = q * TT + j;
            int cur = tg[s];
            int prev = (s == 0) ? START_TAG : tg[s - 1];
            gold += emb[s * TT + cur] + trans[prev * TT + cur];
        }
        if (j == 0) gold += trans[tg[SS - 1] * TT + END_TAG];

        if (j < 4) red[j] = 1.0f;
        alpha[0][j] = (j == START_TAG) ? 1.f : 0.f;
        __syncthreads();

        int le = 0;
        float b0 = emb[1 * TT + j];
        float b1 = emb[2 * TT + j];
        float b2 = emb[3 * TT + j];
        float b3 = emb[4 * TT + j];
        float* a0p = alpha[0];
        float* a1p = alpha[1];

#pragma unroll 1
        for (int g = 0; g < 223; g++) {
            float sc;
            consume_max(red, le, sc);
            float e0 = __expf(b0) * sc;
            float e1 = __expf(b1);
            float e2 = __expf(b2);
            float e3 = __expf(b3);
            const float* pe = emb + (size_t)(4 * g + 5) * TT + j;
            float n0 = pe[0 * TT];
            float n1 = pe[1 * TT];
            float n2 = pe[2 * TT];
            float n3 = pe[3 * TT];
            crf_step<false>(a0p, a1p, E, e0, j, red);
            crf_step<false>(a1p, a0p, E, e1, j, red);
            crf_step<false>(a0p, a1p, E, e2, j, red);
            crf_step<true >(a1p, a0p, E, e3, j, red);
            b0 = n0; b1 = n1; b2 = n2; b3 = n3;
        }
        // final group: t = 893..896 (no prefetch, no renorm publish)
        {
            float sc;
            consume_max(red, le, sc);
            float e0 = __expf(b0) * sc;
            float e1 = __expf(b1);
            float e2 = __expf(b2);
            float e3 = __expf(b3);
            crf_step<false>(a0p, a1p, E, e0, j, red);
            crf_step<false>(a1p, a0p, E, e1, j, red);
            crf_step<false>(a0p, a1p, E, e2, j, red);
            crf_step<false>(a1p, a0p, E, e3, j, red);
        }
        // A_896 lives in alpha[0]
        g_avec[r][j] = a0p[j];

        float y = gold;
#pragma unroll
        for (int o = 16; o > 0; o >>= 1)
            y += __shfl_xor_sync(0xffffffffu, y, o);
        if ((j & 31) == 0) red[4 + (j >> 5)] = y;
        __syncthreads();
        if (j == 0) {
            g_gold[r] = red[4] + red[5] + red[6] + red[7];
            g_lea[r] = le;
        }
        join_row(r, mTE, le, j, red, out);
    } else {
        // ============ BACKWARD: rows bid-256 + 40k, t = 1023..897 ============
#pragma unroll 1
        for (int r = bid - NB; r < NB; r += NBWD) {
            const float* emb = em + (size_t)r * SS * TT;
            __syncthreads();
            if (j < 4) red[j] = 1.0f;
            // B~_1023[j] = exp(em_1023[j] + tE[j] - mTE)
            alpha[0][j] = __expf(emb[1023 * TT + j] + tE - mTE);
            __syncthreads();

            int le = 0;
            // scaled steps s = 0..125 consume emissions t = 1022 - s
            float b0 = emb[1022 * TT + j];
            float b1 = emb[1021 * TT + j];
            float b2 = emb[1020 * TT + j];
            float b3 = emb[1019 * TT + j];
            float* a0p = alpha[0];
            float* a1p = alpha[1];

#pragma unroll 1
            for (int g = 0; g < 30; g++) {
                float sc;
                consume_max(red, le, sc);
                float e0 = __expf(b0) * sc;
                float e1 = __expf(b1);
                float e2 = __expf(b2);
                float e3 = __expf(b3);
                const float* pe = emb + (size_t)(1018 - 4 * g) * TT + j;
                float n0 = pe[0];
                float n1 = pe[-1 * TT];
                float n2 = pe[-2 * TT];
                float n3 = pe[-3 * TT];
                crf_step<false>(a0p, a1p, E, e0, j, red);
                crf_step<false>(a1p, a0p, E, e1, j, red);
                crf_step<false>(a0p, a1p, E, e2, j, red);
                crf_step<true >(a1p, a0p, E, e3, j, red);
                b0 = n0; b1 = n1; b2 = n2; b3 = n3;
            }
            // group 30: s = 120..123 (t = 902..899), prefetch t = 898, 897
            float m0 = emb[898 * TT + j];
            float m1 = emb[897 * TT + j];
            {
                float sc;
                consume_max(red, le, sc);
                float e0 = __expf(b0) * sc;
                float e1 = __expf(b1);
                float e2 = __expf(b2);
                float e3 = __expf(b3);
                crf_step<false>(a0p, a1p, E, e0, j, red);
                crf_step<false>(a1p, a0p, E, e1, j, red);
                crf_step<false>(a0p, a1p, E, e2, j, red);
                crf_step<true >(a1p, a0p, E, e3, j, red);
            }
            // tail: s = 124, 125 (t = 898, 897)
            {
                float sc;
                consume_max(red, le, sc);
                crf_step<false>(a0p, a1p, E, __expf(m0) * sc, j, red);
                crf_step<false>(a1p, a0p, E, __expf(m1), j, red);
            }
            // B~_897 in alpha[0]; final plain matvec: B_896[j] = sum_k E[j,k]*B~_897[k]
            float v = dotrow(a0p, E);
            g_bvec[r][j] = v;
            if (j == 0) g_leb[r] = le;

            join_row(r, mTE, le, j, red, out);
        }
    }
}

extern "C" void kernel_launch(void* const* d_in, const int* in_sizes, int n_in,
                              void* d_out, int out_size) {
    const float* em = (const float*)d_in[0];     // [256,1024,128] f32
    const int* tags = (const int*)d_in[1];       // [256,1024] i32
    const float* trans = (const float*)d_in[2];  // [128,128] f32
    crf_kernel<<<GRID, 128>>>(em, tags, trans, (float*)d_out);
}

// round 13
// speedup vs baseline: 1.4769x; 1.0487x over previous
#include <cuda_runtime.h>

// CRF loss, linear-domain scan — rebalanced fwd/bwd split (F=908) with
// exponent-of-alpha[0] group-top renorm (exact power-of-2, no redux).
// grid = 296 (2 CTAs/SM): bids 0..255 FORWARD scan row bid (t=1..908);
// bids 256..295 BACKWARD scan rows (bid-256)+40k (init t=1023, 114 scaled
// steps to t=909, final plain matvec -> B_908). Join: Z = sum A_908*B_908.

namespace {
constexpr int TT = 128;
constexpr int SS = 1024;
constexpr int NB = 256;
constexpr int NBWD = 40;
constexpr int GRID = NB + NBWD;  // 296 = 2 * 148
constexpr int START_TAG = 126;
constexpr int END_TAG = 127;
}

typedef unsigned long long ull;
__device__ float g_avec[NB][TT];
__device__ float g_bvec[NB][TT];
__device__ int g_lea[NB];
__device__ int g_leb[NB];
__device__ float g_gold[NB];
__device__ double g_part[NB];
__device__ unsigned int g_cnt[NB];
__device__ unsigned int g_ticket;

__device__ __forceinline__ ull pack2f(float lo, float hi) {
    ull r;
    asm("mov.b64 %0, {%1, %2};" : "=l"(r) : "f"(lo), "f"(hi));
    return r;
}

// dot of shared vec[0..127] with this thread's E pairs; 8 accumulators.
__device__ __forceinline__ float dotrow(const float* __restrict__ ar,
                                        const ull* __restrict__ E) {
    ull acc[8];
#pragma unroll
    for (int i = 0; i < 8; i++) acc[i] = 0ull;
    const double2* ap = reinterpret_cast<const double2*>(ar);
#pragma unroll
    for (int k = 0; k < 16; k++) {
        double2 a = ap[2 * k];
        double2 b = ap[2 * k + 1];
        ull a0 = __double_as_longlong(a.x);
        ull a1 = __double_as_longlong(a.y);
        ull b0 = __double_as_longlong(b.x);
        ull b1 = __double_as_longlong(b.y);
        asm("fma.rn.f32x2 %0, %1, %2, %0;" : "+l"(acc[(4 * k + 0) & 7]) : "l"(a0), "l"(E[4 * k + 0]));
        asm("fma.rn.f32x2 %0, %1, %2, %0;" : "+l"(acc[(4 * k + 1) & 7]) : "l"(a1), "l"(E[4 * k + 1]));
        asm("fma.rn.f32x2 %0, %1, %2, %0;" : "+l"(acc[(4 * k + 2) & 7]) : "l"(b0), "l"(E[4 * k + 2]));
        asm("fma.rn.f32x2 %0, %1, %2, %0;" : "+l"(acc[(4 * k + 3) & 7]) : "l"(b1), "l"(E[4 * k + 3]));
    }
    asm("add.rn.f32x2 %0, %0, %1;" : "+l"(acc[0]) : "l"(acc[4]));
    asm("add.rn.f32x2 %0, %0, %1;" : "+l"(acc[1]) : "l"(acc[5]));
    asm("add.rn.f32x2 %0, %0, %1;" : "+l"(acc[2]) : "l"(acc[6]));
    asm("add.rn.f32x2 %0, %0, %1;" : "+l"(acc[3]) : "l"(acc[7]));
    asm("add.rn.f32x2 %0, %0, %1;" : "+l"(acc[0]) : "l"(acc[2]));
    asm("add.rn.f32x2 %0, %0, %1;" : "+l"(acc[1]) : "l"(acc[3]));
    asm("add.rn.f32x2 %0, %0, %1;" : "+l"(acc[0]) : "l"(acc[1]));
    float lo, hi;
    asm("mov.b64 {%0, %1}, %2;" : "=f"(lo), "=f"(hi) : "l"(acc[0]));
    return lo + hi;
}

__device__ __forceinline__ void crf_step(const float* __restrict__ ar,
                                         float* __restrict__ aw,
                                         const ull* __restrict__ E,
                                         float expem, int j) {
    float v = dotrow(ar, E) * expem;
    aw[j] = v;
    __syncthreads();
}

// Group-top renorm scale: exponent of alpha[0] (dense positive after step 1).
// Exact power-of-2; le absorbs it. Clamped for safety.
__device__ __forceinline__ float topscale(const float* __restrict__ ar, int& le) {
    unsigned int bits = __float_as_uint(ar[0]);
    int ex = (int)((bits >> 23) & 0xffu) - 127;
    ex = max(-100, min(100, ex));
    le += ex;
    return __int_as_float((127 - ex) << 23);
}

// Per-row join (second arriver reduces); last row triggers the global mean.
__device__ __forceinline__ void join_row(int r, float mTE, int j,
                                         float* red, float* out) {
    __shared__ int sjoin, sfinal;
    __threadfence();
    __syncthreads();
    if (j == 0) sjoin = (atomicAdd(&g_cnt[r], 1u) == 1u) ? 1 : 0;
    __syncthreads();
    if (!sjoin) return;
    __threadfence();
    float p = __ldcg(&g_avec[r][j]) * __ldcg(&g_bvec[r][j]);
#pragma unroll
    for (int o = 16; o > 0; o >>= 1)
        p += __shfl_xor_sync(0xffffffffu, p, o);
    if ((j & 31) == 0) red[j >> 5] = p;
    __syncthreads();
    if (j == 0) {
        float s = red[0] + red[1] + red[2] + red[3];
        int lt = __ldcg(&g_lea[r]) + __ldcg(&g_leb[r]);
        double part = (double)lt * 0.6931471805599453 + (double)mTE +
                      log((double)s) - (double)__ldcg(&g_gold[r]);
        g_part[r] = part;
        g_cnt[r] = 0;
        __threadfence();
        sfinal = (atomicAdd(&g_ticket, 1u) == NB - 1) ? 1 : 0;
    }
    __syncthreads();
    if (sfinal) {
        __threadfence();
        double d = __ldcg(&g_part[j]) + __ldcg(&g_part[j + 128]);
#pragma unroll
        for (int o = 16; o > 0; o >>= 1)
            d += __shfl_xor_sync(0xffffffffu, d, o);
        __shared__ double sd[4];
        if ((j & 31) == 0) sd[j >> 5] = d;
        __syncthreads();
        if (j == 0) {
            out[0] = (float)((sd[0] + sd[1] + sd[2] + sd[3]) * (1.0 / NB));
            g_ticket = 0;  // reset for graph replay
        }
    }
    __syncthreads();
}

__global__ void __launch_bounds__(128, 2)
crf_kernel(const float* __restrict__ em, const int* __restrict__ tags,
           const float* __restrict__ trans, float* __restrict__ out) {
    const int bid = blockIdx.x;
    const int j = threadIdx.x;
    __shared__ __align__(16) float alpha[2][TT];
    __shared__ __align__(16) float red[8];

    const bool isFwd = (bid < NB);

    // E pairs: fwd thread j owns column j (pairs over i); bwd thread j owns
    // row j (pairs over k) for the transposed matvec.
    ull E[64];
    if (isFwd) {
#pragma unroll
        for (int k = 0; k < 64; k++)
            E[k] = pack2f(__expf(trans[(2 * k) * TT + j]),
                          __expf(trans[(2 * k + 1) * TT + j]));
    } else {
#pragma unroll
        for (int k = 0; k < 64; k++)
            E[k] = pack2f(__expf(trans[j * TT + 2 * k]),
                          __expf(trans[j * TT + 2 * k + 1]));
    }

    // one-time: max of END transition row
    float tE = trans[END_TAG * TT + j];
    {
        float m = tE;
#pragma unroll
        for (int o = 16; o > 0; o >>= 1)
            m = fmaxf(m, __shfl_xor_sync(0xffffffffu, m, o));
        if ((j & 31) == 0) red[j >> 5] = m;
    }
    __syncthreads();
    const float mTE = fmaxf(fmaxf(red[0], red[1]), fmaxf(red[2], red[3]));
    __syncthreads();

    if (isFwd) {
        // ================ FORWARD: row bid, t = 1..908 ================
        const int r = bid;
        const float* emb = em + (size_t)r * SS * TT;
        const int* tg = tags + r * SS;

        // gold path score (full row)
        float gold = 0.f;
#pragma unroll
        for (int q = 0; q < SS / TT; q++) {
            int s = q * TT + j;
            int cur = tg[s];
            int prev = (s == 0) ? START_TAG : tg[s - 1];
            gold += emb[s * TT + cur] + trans[prev * TT + cur];
        }
        if (j == 0) gold += trans[tg[SS - 1] * TT + END_TAG];

        alpha[0][j] = (j == START_TAG) ? 1.f : 0.f;
        __syncthreads();

        int le = 0;
        float b0 = emb[1 * TT + j];
        float b1 = emb[2 * TT + j];
        float b2 = emb[3 * TT + j];
        float b3 = emb[4 * TT + j];
        float* a0p = alpha[0];
        float* a1p = alpha[1];

        // group 0 (t = 1..4): sc = 1 (alpha one-hot, skip exponent renorm)
        {
            float e0 = __expf(b0);
            float e1 = __expf(b1);
            float e2 = __expf(b2);
            float e3 = __expf(b3);
            const float* pe = emb + (size_t)5 * TT + j;
            float n0 = pe[0 * TT];
            float n1 = pe[1 * TT];
            float n2 = pe[2 * TT];
            float n3 = pe[3 * TT];
            crf_step(a0p, a1p, E, e0, j);
            crf_step(a1p, a0p, E, e1, j);
            crf_step(a0p, a1p, E, e2, j);
            crf_step(a1p, a0p, E, e3, j);
            b0 = n0; b1 = n1; b2 = n2; b3 = n3;
        }
        // groups 1..225 (t = 5..904) with prefetch
#pragma unroll 1
        for (int g = 1; g < 226; g++) {
            float sc = topscale(a0p, le);
            float e0 = __expf(b0) * sc;
            float e1 = __expf(b1);
            float e2 = __expf(b2);
            float e3 = __expf(b3);
            const float* pe = emb + (size_t)(4 * g + 5) * TT + j;
            float n0 = pe[0 * TT];
            float n1 = pe[1 * TT];
            float n2 = pe[2 * TT];
            float n3 = pe[3 * TT];
            crf_step(a0p, a1p, E, e0, j);
            crf_step(a1p, a0p, E, e1, j);
            crf_step(a0p, a1p, E, e2, j);
            crf_step(a1p, a0p, E, e3, j);
            b0 = n0; b1 = n1; b2 = n2; b3 = n3;
        }
        // group 226 (t = 905..908), no prefetch
        {
            float sc = topscale(a0p, le);
            float e0 = __expf(b0) * sc;
            float e1 = __expf(b1);
            float e2 = __expf(b2);
            float e3 = __expf(b3);
            crf_step(a0p, a1p, E, e0, j);
            crf_step(a1p, a0p, E, e1, j);
            crf_step(a0p, a1p, E, e2, j);
            crf_step(a1p, a0p, E, e3, j);
        }
        // A_908 in alpha[0]
        g_avec[r][j] = a0p[j];

        float y = gold;
#pragma unroll
        for (int o = 16; o > 0; o >>= 1)
            y += __shfl_xor_sync(0xffffffffu, y, o);
        if ((j & 31) == 0) red[4 + (j >> 5)] = y;
        __syncthreads();
        if (j == 0) {
            g_gold[r] = red[4] + red[5] + red[6] + red[7];
            g_lea[r] = le;
        }
        join_row(r, mTE, j, red, out);
    } else {
        // ========= BACKWARD: rows (bid-256)+40k, t = 1023..909 =========
#pragma unroll 1
        for (int r = bid - NB; r < NB; r += NBWD) {
            const float* emb = em + (size_t)r * SS * TT;
            __syncthreads();
            // B~_1023[j] = exp(em_1023[j] + tE[j] - mTE)
            alpha[0][j] = __expf(emb[1023 * TT + j] + tE - mTE);
            __syncthreads();

            int le = 0;
            float b0 = emb[1022 * TT + j];
            float b1 = emb[1021 * TT + j];
            float b2 = emb[1020 * TT + j];
            float b3 = emb[1019 * TT + j];
            float* a0p = alpha[0];
            float* a1p = alpha[1];

            // group 0 (t = 1022..1019): sc = 1
            {
                float e0 = __expf(b0);
                float e1 = __expf(b1);
                float e2 = __expf(b2);
                float e3 = __expf(b3);
                const float* pe = emb + (size_t)1018 * TT + j;
                float n0 = pe[0];
                float n1 = pe[-1 * TT];
                float n2 = pe[-2 * TT];
                float n3 = pe[-3 * TT];
                crf_step(a0p, a1p, E, e0, j);
                crf_step(a1p, a0p, E, e1, j);
                crf_step(a0p, a1p, E, e2, j);
                crf_step(a1p, a0p, E, e3, j);
                b0 = n0; b1 = n1; b2 = n2; b3 = n3;
            }
            // groups 1..26 (t = 1018..915) with prefetch
#pragma unroll 1
            for (int g = 1; g < 27; g++) {
                float sc = topscale(a0p, le);
                float e0 = __expf(b0) * sc;
                float e1 = __expf(b1);
                float e2 = __expf(b2);
                float e3 = __expf(b3);
                const float* pe = emb + (size_t)(1018 - 4 * g) * TT + j;
                float n0 = pe[0];
                float n1 = pe[-1 * TT];
                float n2 = pe[-2 * TT];
                float n3 = pe[-3 * TT];
                crf_step(a0p, a1p, E, e0, j);
                crf_step(a1p, a0p, E, e1, j);
                crf_step(a0p, a1p, E, e2, j);
                crf_step(a1p, a0p, E, e3, j);
                b0 = n0; b1 = n1; b2 = n2; b3 = n3;
            }
            // group 27 (t = 914..911), prefetch remainder t = 910, 909
            float m0 = emb[910 * TT + j];
            float m1 = emb[909 * TT + j];
            {
                float sc = topscale(a0p, le);
                float e0 = __expf(b0) * sc;
                float e1 = __expf(b1);
                float e2 = __expf(b2);
                float e3 = __expf(b3);
                crf_step(a0p, a1p, E, e0, j);
                crf_step(a1p, a0p, E, e1, j);
                crf_step(a0p, a1p, E, e2, j);
                crf_step(a1p, a0p, E, e3, j);
            }
            // remainder (t = 910, 909)
            {
                float sc = topscale(a0p, le);
                crf_step(a0p, a1p, E, __expf(m0) * sc, j);
                crf_step(a1p, a0p, E, __expf(m1), j);
            }
            // B~_909 in alpha[0]; final plain matvec: B_908 = E * B~_909
            float v = dotrow(a0p, E);
            g_bvec[r][j] = v;
            if (j == 0) g_leb[r] = le;

            join_row(r, mTE, j, red, out);
        }
    }
}

extern "C" void kernel_launch(void* const* d_in, const int* in_sizes, int n_in,
                              void* d_out, int out_size) {
    const float* em = (const float*)d_in[0];     // [256,1024,128] f32
    const int* tags = (const int*)d_in[1];       // [256,1024] i32
    const float* trans = (const float*)d_in[2];  // [128,128] f32
    crf_kernel<<<GRID, 128>>>(em, tags, trans, (float*)d_out);
}

// round 14
// speedup vs baseline: 2.0187x; 1.3669x over previous
#include <cuda_runtime.h>
#include <cuda_bf16.h>

// CRF loss, linear-domain scan — fwd/bwd split (F=908) with bf16 inner dot.
// E = exp(trans) and the alpha vector are bf16 (HFMA2 pipe, rt=2, half the
// LDS traffic); emission multipliers, renorm scale (exact power-of-2 via
// exponent of alpha[0]), le accounting, gold score and final logs stay
// fp32/double. grid = 296 (2 CTAs/SM): bids 0..255 FORWARD rows (t=1..908);
// bids 256..295 BACKWARD rows (bid-256)+40k (t=1023 init, scaled to t=909,
// final plain matvec). Join per row: Z = sum_j A908[j]*B908[j].

namespace {
constexpr int TT = 128;
constexpr int SS = 1024;
constexpr int NB = 256;
constexpr int NBWD = 40;
constexpr int GRID = NB + NBWD;  // 296 = 2 * 148
constexpr int START_TAG = 126;
constexpr int END_TAG = 127;
}

typedef unsigned int u32;
__device__ float g_avec[NB][TT];
__device__ float g_bvec[NB][TT];
__device__ int g_lea[NB];
__device__ int g_leb[NB];
__device__ float g_gold[NB];
__device__ double g_part[NB];
__device__ unsigned int g_cnt[NB];
__device__ unsigned int g_ticket;

__device__ __forceinline__ __nv_bfloat162 u2bf2(u32 x) {
    __nv_bfloat162 r;
    *reinterpret_cast<u32*>(&r) = x;
    return r;
}

// bf16 dot of shared alpha (128 bf16 = 16 x LDS.128) with this thread's
// 64 bf16x2 E pairs; 8 bf16x2 accumulators, f32 finish.
__device__ __forceinline__ float dotrow(const uint4* __restrict__ ap,
                                        const __nv_bfloat162* __restrict__ E) {
    __nv_bfloat162 acc[8];
#pragma unroll
    for (int i = 0; i < 8; i++) acc[i] = u2bf2(0u);
#pragma unroll
    for (int k = 0; k < 16; k++) {
        uint4 q = ap[k];
        acc[(4 * k + 0) & 7] = __hfma2(u2bf2(q.x), E[4 * k + 0], acc[(4 * k + 0) & 7]);
        acc[(4 * k + 1) & 7] = __hfma2(u2bf2(q.y), E[4 * k + 1], acc[(4 * k + 1) & 7]);
        acc[(4 * k + 2) & 7] = __hfma2(u2bf2(q.z), E[4 * k + 2], acc[(4 * k + 2) & 7]);
        acc[(4 * k + 3) & 7] = __hfma2(u2bf2(q.w), E[4 * k + 3], acc[(4 * k + 3) & 7]);
    }
    acc[0] = __hadd2(acc[0], acc[4]);
    acc[1] = __hadd2(acc[1], acc[5]);
    acc[2] = __hadd2(acc[2], acc[6]);
    acc[3] = __hadd2(acc[3], acc[7]);
    acc[0] = __hadd2(acc[0], acc[2]);
    acc[1] = __hadd2(acc[1], acc[3]);
    acc[0] = __hadd2(acc[0], acc[1]);
    float2 f = __bfloat1622float2(acc[0]);
    return f.x + f.y;
}

// One step: v = dot(alpha_bf16, E) * expem (f32), stored back as bf16.
__device__ __forceinline__ void crf_step(const __nv_bfloat16* __restrict__ ar,
                                         __nv_bfloat16* __restrict__ aw,
                                         const __nv_bfloat162* __restrict__ E,
                                         float expem, int j) {
    float v = dotrow(reinterpret_cast<const uint4*>(ar), E) * expem;
    aw[j] = __float2bfloat16_rn(v);
    __syncthreads();
}

// Group-top renorm scale from exponent of alpha[0] (bf16 bits; exponent field
// identical to f32). Exact power-of-2; le absorbs it. Clamped for safety.
__device__ __forceinline__ float topscale(const __nv_bfloat16* __restrict__ ar,
                                          int& le) {
    unsigned short bits = *reinterpret_cast<const unsigned short*>(ar);
    int ex = (int)((bits >> 7) & 0xffu) - 127;
    ex = max(-100, min(100, ex));
    le += ex;
    return __int_as_float((127 - ex) << 23);
}

// Per-row join (second arriver reduces); last row triggers the global mean.
__device__ __forceinline__ void join_row(int r, float mTE, int j,
                                         float* red, float* out) {
    __shared__ int sjoin, sfinal;
    __threadfence();
    __syncthreads();
    if (j == 0) sjoin = (atomicAdd(&g_cnt[r], 1u) == 1u) ? 1 : 0;
    __syncthreads();
    if (!sjoin) return;
    __threadfence();
    float p = __ldcg(&g_avec[r][j]) * __ldcg(&g_bvec[r][j]);
#pragma unroll
    for (int o = 16; o > 0; o >>= 1)
        p += __shfl_xor_sync(0xffffffffu, p, o);
    if ((j & 31) == 0) red[j >> 5] = p;
    __syncthreads();
    if (j == 0) {
        float s = red[0] + red[1] + red[2] + red[3];
        int lt = __ldcg(&g_lea[r]) + __ldcg(&g_leb[r]);
        double part = (double)lt * 0.6931471805599453 + (double)mTE +
                      log((double)s) - (double)__ldcg(&g_gold[r]);
        g_part[r] = part;
        g_cnt[r] = 0;
        __threadfence();
        sfinal = (atomicAdd(&g_ticket, 1u) == NB - 1) ? 1 : 0;
    }
    __syncthreads();
    if (sfinal) {
        __threadfence();
        double d = __ldcg(&g_part[j]) + __ldcg(&g_part[j + 128]);
#pragma unroll
        for (int o = 16; o > 0; o >>= 1)
            d += __shfl_xor_sync(0xffffffffu, d, o);
        __shared__ double sd[4];
        if ((j & 31) == 0) sd[j >> 5] = d;
        __syncthreads();
        if (j == 0) {
            out[0] = (float)((sd[0] + sd[1] + sd[2] + sd[3]) * (1.0 / NB));
            g_ticket = 0;  // reset for graph replay
        }
    }
    __syncthreads();
}

__global__ void __launch_bounds__(128, 2)
crf_kernel(const float* __restrict__ em, const int* __restrict__ tags,
           const float* __restrict__ trans, float* __restrict__ out) {
    const int bid = blockIdx.x;
    const int j = threadIdx.x;
    __shared__ __align__(16) __nv_bfloat16 alpha[2][TT];
    __shared__ __align__(16) float red[8];

    const bool isFwd = (bid < NB);

    // E pairs in bf16x2: fwd thread j owns column j (pairs over i);
    // bwd thread j owns row j (pairs over k) for the transposed matvec.
    __nv_bfloat162 E[64];
    if (isFwd) {
#pragma unroll
        for (int k = 0; k < 64; k++)
            E[k] = __floats2bfloat162_rn(__expf(trans[(2 * k) * TT + j]),
                                         __expf(trans[(2 * k + 1) * TT + j]));
    } else {
#pragma unroll
        for (int k = 0; k < 64; k++)
            E[k] = __floats2bfloat162_rn(__expf(trans[j * TT + 2 * k]),
                                         __expf(trans[j * TT + 2 * k + 1]));
    }

    // one-time: max of END transition row
    float tE = trans[END_TAG * TT + j];
    {
        float m = tE;
#pragma unroll
        for (int o = 16; o > 0; o >>= 1)
            m = fmaxf(m, __shfl_xor_sync(0xffffffffu, m, o));
        if ((j & 31) == 0) red[j >> 5] = m;
    }
    __syncthreads();
    const float mTE = fmaxf(fmaxf(red[0], red[1]), fmaxf(red[2], red[3]));
    __syncthreads();

    if (isFwd) {
        // ================ FORWARD: row bid, t = 1..908 ================
        const int r = bid;
        const float* emb = em + (size_t)r * SS * TT;
        const int* tg = tags + r * SS;

        // gold path score (full row, fp32 exact)
        float gold = 0.f;
#pragma unroll
        for (int q = 0; q < SS / TT; q++) {
            int s = q * TT + j;
            int cur = tg[s];
            int prev = (s == 0) ? START_TAG : tg[s - 1];
            gold += emb[s * TT + cur] + trans[prev * TT + cur];
        }
        if (j == 0) gold += trans[tg[SS - 1] * TT + END_TAG];

        alpha[0][j] = __float2bfloat16_rn((j == START_TAG) ? 1.f : 0.f);
        __syncthreads();

        int le = 0;
        float b0 = emb[1 * TT + j];
        float b1 = emb[2 * TT + j];
        float b2 = emb[3 * TT + j];
        float b3 = emb[4 * TT + j];
        __nv_bfloat16* a0p = alpha[0];
        __nv_bfloat16* a1p = alpha[1];

        // group 0 (t = 1..4): sc = 1 (alpha one-hot)
        {
            float e0 = __expf(b0);
            float e1 = __expf(b1);
            float e2 = __expf(b2);
            float e3 = __expf(b3);
            const float* pe = emb + (size_t)5 * TT + j;
            float n0 = pe[0 * TT];
            float n1 = pe[1 * TT];
            float n2 = pe[2 * TT];
            float n3 = pe[3 * TT];
            crf_step(a0p, a1p, E, e0, j);
            crf_step(a1p, a0p, E, e1, j);
            crf_step(a0p, a1p, E, e2, j);
            crf_step(a1p, a0p, E, e3, j);
            b0 = n0; b1 = n1; b2 = n2; b3 = n3;
        }
        // groups 1..225 (t = 5..904) with prefetch
#pragma unroll 1
        for (int g = 1; g < 226; g++) {
            float sc = topscale(a0p, le);
            float e0 = __expf(b0) * sc;
            float e1 = __expf(b1);
            float e2 = __expf(b2);
            float e3 = __expf(b3);
            const float* pe = emb + (size_t)(4 * g + 5) * TT + j;
            float n0 = pe[0 * TT];
            float n1 = pe[1 * TT];
            float n2 = pe[2 * TT];
            float n3 = pe[3 * TT];
            crf_step(a0p, a1p, E, e0, j);
            crf_step(a1p, a0p, E, e1, j);
            crf_step(a0p, a1p, E, e2, j);
            crf_step(a1p, a0p, E, e3, j);
            b0 = n0; b1 = n1; b2 = n2; b3 = n3;
        }
        // group 226 (t = 905..908), no prefetch
        {
            float sc = topscale(a0p, le);
            float e0 = __expf(b0) * sc;
            float e1 = __expf(b1);
            float e2 = __expf(b2);
            float e3 = __expf(b3);
            crf_step(a0p, a1p, E, e0, j);
            crf_step(a1p, a0p, E, e1, j);
            crf_step(a0p, a1p, E, e2, j);
            crf_step(a1p, a0p, E, e3, j);
        }
        // A_908 in alpha[0]
        g_avec[r][j] = __bfloat162float(a0p[j]);

        float y = gold;
#pragma unroll
        for (int o = 16; o > 0; o >>= 1)
            y += __shfl_xor_sync(0xffffffffu, y, o);
        if ((j & 31) == 0) red[4 + (j >> 5)] = y;
        __syncthreads();
        if (j == 0) {
            g_gold[r] = red[4] + red[5] + red[6] + red[7];
            g_lea[r] = le;
        }
        join_row(r, mTE, j, red, out);
    } else {
        // ========= BACKWARD: rows (bid-256)+40k, t = 1023..909 =========
#pragma unroll 1
        for (int r = bid - NB; r < NB; r += NBWD) {
            const float* emb = em + (size_t)r * SS * TT;
            __syncthreads();
            // B~_1023[j] = exp(em_1023[j] + tE[j] - mTE)
            alpha[0][j] = __float2bfloat16_rn(__expf(emb[1023 * TT + j] + tE - mTE));
            __syncthreads();

            int le = 0;
            float b0 = emb[1022 * TT + j];
            float b1 = emb[1021 * TT + j];
            float b2 = emb[1020 * TT + j];
            float b3 = emb[1019 * TT + j];
            __nv_bfloat16* a0p = alpha[0];
            __nv_bfloat16* a1p = alpha[1];

            // group 0 (t = 1022..1019): sc = 1
            {
                float e0 = __expf(b0);
                float e1 = __expf(b1);
                float e2 = __expf(b2);
                float e3 = __expf(b3);
                const float* pe = emb + (size_t)1018 * TT + j;
                float n0 = pe[0];
                float n1 = pe[-1 * TT];
                float n2 = pe[-2 * TT];
                float n3 = pe[-3 * TT];
                crf_step(a0p, a1p, E, e0, j);
                crf_step(a1p, a0p, E, e1, j);
                crf_step(a0p, a1p, E, e2, j);
                crf_step(a1p, a0p, E, e3, j);
                b0 = n0; b1 = n1; b2 = n2; b3 = n3;
            }
            // groups 1..26 (t = 1018..915) with prefetch
#pragma unroll 1
            for (int g = 1; g < 27; g++) {
                float sc = topscale(a0p, le);
                float e0 = __expf(b0) * sc;
                float e1 = __expf(b1);
                float e2 = __expf(b2);
                float e3 = __expf(b3);
                const float* pe = emb + (size_t)(1018 - 4 * g) * TT + j;
                float n0 = pe[0];
                float n1 = pe[-1 * TT];
                float n2 = pe[-2 * TT];
                float n3 = pe[-3 * TT];
                crf_step(a0p, a1p, E, e0, j);
                crf_step(a1p, a0p, E, e1, j);
                crf_step(a0p, a1p, E, e2, j);
                crf_step(a1p, a0p, E, e3, j);
                b0 = n0; b1 = n1; b2 = n2; b3 = n3;
            }
            // group 27 (t = 914..911), prefetch remainder t = 910, 909
            float m0 = emb[910 * TT + j];
            float m1 = emb[909 * TT + j];
            {
                float sc = topscale(a0p, le);
                float e0 = __expf(b0) * sc;
                float e1 = __expf(b1);
                float e2 = __expf(b2);
                float e3 = __expf(b3);
                crf_step(a0p, a1p, E, e0, j);
                crf_step(a1p, a0p, E, e1, j);
                crf_step(a0p, a1p, E, e2, j);
                crf_step(a1p, a0p, E, e3, j);
            }
            // remainder (t = 910, 909)
            {
                float sc = topscale(a0p, le);
                crf_step(a0p, a1p, E, __expf(m0) * sc, j);
                crf_step(a1p, a0p, E, __expf(m1), j);
            }
            // B~_909 in alpha[0]; final plain matvec: B_908 = E * B~_909
            float v = dotrow(reinterpret_cast<const uint4*>(a0p), E);
            g_bvec[r][j] = v;
            if (j == 0) g_leb[r] = le;

            join_row(r, mTE, j, red, out);
        }
    }
}

extern "C" void kernel_launch(void* const* d_in, const int* in_sizes, int n_in,
                              void* d_out, int out_size) {
    const float* em = (const float*)d_in[0];     // [256,1024,128] f32
    const int* tags = (const int*)d_in[1];       // [256,1024] i32
    const float* trans = (const float*)d_in[2];  // [128,128] f32
    crf_kernel<<<GRID, 128>>>(em, tags, trans, (float*)d_out);
}